// round 7
// baseline (speedup 1.0000x reference)
#include <cuda_runtime.h>
#include <cstdint>

// Problem sizes (fixed by the reference)
#define NNODES 50000
#define NREL   8
#define DIM    128
#define NEDGE  800000
#define NTRIP  100000
#define KTOT   1152          // NREL*DIM + DIM (root folded as 9th block)
#define NSEG   (NNODES * NREL)          // 400000
#define NBLK   ((NSEG + 1023) / 1024)   // 391

// ---------------- scratch (static device globals; no allocs allowed) -------
__device__ __align__(16) float g_h1[(size_t)NNODES * DIM];   // 25.6 MB
__device__ __align__(16) float g_h2[(size_t)NNODES * DIM];   // 25.6 MB
__device__ __align__(16) float g_WT0[(size_t)DIM * KTOT];    // (W0||root0)^T tf32
__device__ __align__(16) float g_WT1[(size_t)DIM * KTOT];    // (W1||root1)^T tf32
__device__ int g_cnt[NSEG];     // per-(dst,rel) edge count
__device__ int g_off[NSEG];     // CSR exclusive offsets
__device__ int g_fill[NSEG];    // fill cursors
__device__ int g_csr[NEDGE];    // src node per CSR slot
__device__ int g_bsum[NBLK];
__device__ int g_bbase[NBLK];

// ---------------- W||root transpose + tf32 round --------------------------
__global__ void transpose_w(const float* __restrict__ W0,
                            const float* __restrict__ root0,
                            const float* __restrict__ W1,
                            const float* __restrict__ root1) {
    int b = blockIdx.x;
    int layer = b / KTOT;
    int k = b % KTOT;
    const float* src;
    if (layer == 0)
        src = (k < NREL * DIM) ? (W0 + (size_t)k * DIM)
                               : (root0 + (size_t)(k - NREL * DIM) * DIM);
    else
        src = (k < NREL * DIM) ? (W1 + (size_t)k * DIM)
                               : (root1 + (size_t)(k - NREL * DIM) * DIM);
    float v = src[threadIdx.x];
    uint32_t t;
    asm("cvt.rna.tf32.f32 %0, %1;" : "=r"(t) : "f"(v));
    float* dst = layer ? g_WT1 : g_WT0;
    dst[(size_t)threadIdx.x * KTOT + k] = __uint_as_float(t);
}

// ---------------- CSR build -----------------------------------------------
__global__ void csr_zero() {
    for (int i = blockIdx.x * blockDim.x + threadIdx.x; i < NSEG;
         i += gridDim.x * blockDim.x) {
        g_cnt[i] = 0;
        g_fill[i] = 0;
    }
}
__global__ void csr_hist(const int* __restrict__ ei,
                         const int* __restrict__ et) {
    int e = blockIdx.x * blockDim.x + threadIdx.x;
    if (e >= NEDGE) return;
    int seg = ei[NEDGE + e] * NREL + et[e];
    atomicAdd(&g_cnt[seg], 1);
}
__global__ void csr_bsum() {  // grid NBLK x 1024
    __shared__ int sh[1024];
    int gid = blockIdx.x * 1024 + threadIdx.x;
    sh[threadIdx.x] = (gid < NSEG) ? g_cnt[gid] : 0;
    __syncthreads();
    for (int s = 512; s > 0; s >>= 1) {
        if (threadIdx.x < s) sh[threadIdx.x] += sh[threadIdx.x + s];
        __syncthreads();
    }
    if (threadIdx.x == 0) g_bsum[blockIdx.x] = sh[0];
}
__global__ void csr_bscan() {  // 1 block x 512
    __shared__ int sh[512];
    int v = (threadIdx.x < NBLK) ? g_bsum[threadIdx.x] : 0;
    sh[threadIdx.x] = v;
    __syncthreads();
    for (int ofs = 1; ofs < 512; ofs <<= 1) {
        int t = (threadIdx.x >= ofs) ? sh[threadIdx.x - ofs] : 0;
        __syncthreads();
        sh[threadIdx.x] += t;
        __syncthreads();
    }
    if (threadIdx.x < NBLK) g_bbase[threadIdx.x] = sh[threadIdx.x] - v;
}
__global__ void csr_off() {  // grid NBLK x 1024
    __shared__ int sh[1024];
    int gid = blockIdx.x * 1024 + threadIdx.x;
    int v = (gid < NSEG) ? g_cnt[gid] : 0;
    sh[threadIdx.x] = v;
    __syncthreads();
    for (int ofs = 1; ofs < 1024; ofs <<= 1) {
        int t = (threadIdx.x >= ofs) ? sh[threadIdx.x - ofs] : 0;
        __syncthreads();
        sh[threadIdx.x] += t;
        __syncthreads();
    }
    if (gid < NSEG) g_off[gid] = g_bbase[blockIdx.x] + sh[threadIdx.x] - v;
}
__global__ void csr_fill(const int* __restrict__ ei,
                         const int* __restrict__ et) {
    int e = blockIdx.x * blockDim.x + threadIdx.x;
    if (e >= NEDGE) return;
    int seg = ei[NEDGE + e] * NREL + et[e];
    int pos = g_off[seg] + atomicAdd(&g_fill[seg], 1);
    g_csr[pos] = ei[e];
}

// ---------------- fused gather-aggregate-GEMM layer -----------------------
// out[n,:] = relu( [mean_r(h[src]) for r=0..7 || hin[n,:]] @ Wcat + bias )
// BM=128, BN=128, BK=128 (one rel-block / root per iter). 8 warps 4x2,
// warp tile 32x64, m16n8k8 tf32.
#define LDP 132
#define SMEM_TOT (2 * 128 * LDP * 4)   // 135168 B

__device__ __forceinline__ void mma_tf32(float* c, const uint32_t* a,
                                         const uint32_t* b) {
    asm volatile(
        "mma.sync.aligned.m16n8k8.row.col.f32.tf32.tf32.f32 "
        "{%0,%1,%2,%3}, {%4,%5,%6,%7}, {%8,%9}, {%0,%1,%2,%3};"
        : "+f"(c[0]), "+f"(c[1]), "+f"(c[2]), "+f"(c[3])
        : "r"(a[0]), "r"(a[1]), "r"(a[2]), "r"(a[3]), "r"(b[0]), "r"(b[1]));
}
__device__ __forceinline__ uint32_t to_tf32(float f) {
    uint32_t t;
    asm("cvt.rna.tf32.f32 %0, %1;" : "=r"(t) : "f"(f));
    return t;
}

__global__ __launch_bounds__(256) void rgcn_layer_fused(
    const float* __restrict__ hin_ext, int useGin, int wtSel,
    const float* __restrict__ bias, int outSel)
{
    extern __shared__ float smemf[];
    float* smA = smemf;                 // [128][LDP]
    float* smB = smemf + 128 * LDP;     // [128][LDP]

    const int tid  = threadIdx.x;
    const int wid  = tid >> 5;
    const int lane = tid & 31;
    const int g    = lane >> 2;
    const int t4   = lane & 3;
    const int wr   = wid & 3;           // warp row (M: 4 x 32)
    const int wc   = wid >> 2;          // warp col (N: 2 x 64)
    const int row0 = blockIdx.x * 128;

    const float* __restrict__ hin = useGin ? g_h1 : hin_ext;
    const float* __restrict__ WT  = wtSel ? g_WT1 : g_WT0;
    float* __restrict__ hout = outSel ? g_h2 : g_h1;

    float acc[2][8][4];
#pragma unroll
    for (int mt = 0; mt < 2; ++mt)
#pragma unroll
        for (int nt = 0; nt < 8; ++nt)
#pragma unroll
            for (int j = 0; j < 4; ++j) acc[mt][nt][j] = 0.f;

    for (int blk = 0; blk < 9; ++blk) {
        if (blk) __syncthreads();       // prev MMA done before overwrite

        // ---- build A tile (warp w: rows w*16 .. w*16+15) ----
        if (blk < 8) {
#pragma unroll 1
            for (int rr = 0; rr < 16; ++rr) {
                int m = (wid << 4) + rr;
                int n = row0 + m;
                float4 acc4 = make_float4(0.f, 0.f, 0.f, 0.f);
                int c = 0;
                if (n < NNODES) {
                    int seg = n * NREL + blk;
                    int beg = g_off[seg];
                    c = g_cnt[seg];
                    int e = 0;
                    for (; e + 4 <= c; e += 4) {    // MLP-4
                        int s0 = g_csr[beg + e];
                        int s1 = g_csr[beg + e + 1];
                        int s2 = g_csr[beg + e + 2];
                        int s3 = g_csr[beg + e + 3];
                        float4 v0 = reinterpret_cast<const float4*>(
                            hin + (size_t)s0 * DIM)[lane];
                        float4 v1 = reinterpret_cast<const float4*>(
                            hin + (size_t)s1 * DIM)[lane];
                        float4 v2 = reinterpret_cast<const float4*>(
                            hin + (size_t)s2 * DIM)[lane];
                        float4 v3 = reinterpret_cast<const float4*>(
                            hin + (size_t)s3 * DIM)[lane];
                        acc4.x += (v0.x + v1.x) + (v2.x + v3.x);
                        acc4.y += (v0.y + v1.y) + (v2.y + v3.y);
                        acc4.z += (v0.z + v1.z) + (v2.z + v3.z);
                        acc4.w += (v0.w + v1.w) + (v2.w + v3.w);
                    }
                    for (; e < c; ++e) {
                        int s0 = g_csr[beg + e];
                        float4 v0 = reinterpret_cast<const float4*>(
                            hin + (size_t)s0 * DIM)[lane];
                        acc4.x += v0.x; acc4.y += v0.y;
                        acc4.z += v0.z; acc4.w += v0.w;
                    }
                    float inv = 1.0f / (float)max(c, 1);
                    acc4.x *= inv; acc4.y *= inv;
                    acc4.z *= inv; acc4.w *= inv;
                }
                uint4 r;
                r.x = to_tf32(acc4.x); r.y = to_tf32(acc4.y);
                r.z = to_tf32(acc4.z); r.w = to_tf32(acc4.w);
                *reinterpret_cast<uint4*>(smA + m * LDP + lane * 4) = r;
            }
        } else {
            // root block: A = hin rows directly
#pragma unroll 1
            for (int rr = 0; rr < 16; ++rr) {
                int m = (wid << 4) + rr;
                int n = row0 + m;
                float4 v = make_float4(0.f, 0.f, 0.f, 0.f);
                if (n < NNODES)
                    v = reinterpret_cast<const float4*>(
                        hin + (size_t)n * DIM)[lane];
                uint4 r;
                r.x = to_tf32(v.x); r.y = to_tf32(v.y);
                r.z = to_tf32(v.z); r.w = to_tf32(v.w);
                *reinterpret_cast<uint4*>(smA + m * LDP + lane * 4) = r;
            }
        }

        // ---- load B tile: WT[n][kb .. kb+128) ----
        {
            const int kb = blk * 128;
#pragma unroll
            for (int i = 0; i < 16; ++i) {
                int idx = tid + i * 256;         // 0..4095
                int nn = idx >> 5, q = idx & 31;
                float4 w = *reinterpret_cast<const float4*>(
                    WT + (size_t)nn * KTOT + kb + q * 4);
                *reinterpret_cast<float4*>(smB + nn * LDP + q * 4) = w;
            }
        }
        __syncthreads();

        // ---- MMA over BK=128 (16 k-steps) ----
#pragma unroll
        for (int ks = 0; ks < 16; ++ks) {
            const int kk = ks * 8;
            uint32_t a[2][4], b[8][2];
#pragma unroll
            for (int mt = 0; mt < 2; ++mt) {
                int r0 = wr * 32 + mt * 16 + g;
                a[mt][0] = __float_as_uint(smA[(r0)     * LDP + kk + t4]);
                a[mt][1] = __float_as_uint(smA[(r0 + 8) * LDP + kk + t4]);
                a[mt][2] = __float_as_uint(smA[(r0)     * LDP + kk + t4 + 4]);
                a[mt][3] = __float_as_uint(smA[(r0 + 8) * LDP + kk + t4 + 4]);
            }
#pragma unroll
            for (int nt = 0; nt < 8; ++nt) {
                int nn = wc * 64 + nt * 8 + g;
                b[nt][0] = __float_as_uint(smB[nn * LDP + kk + t4]);
                b[nt][1] = __float_as_uint(smB[nn * LDP + kk + t4 + 4]);
            }
#pragma unroll
            for (int mt = 0; mt < 2; ++mt)
#pragma unroll
                for (int nt = 0; nt < 8; ++nt)
                    mma_tf32(acc[mt][nt], a[mt], b[nt]);
        }
    }

    // ---- epilogue: bias + relu, direct from accumulators ----
    float2 bb[8];
#pragma unroll
    for (int nt = 0; nt < 8; ++nt) {
        int col = wc * 64 + nt * 8 + t4 * 2;
        bb[nt].x = __ldg(bias + col);
        bb[nt].y = __ldg(bias + col + 1);
    }
#pragma unroll
    for (int mt = 0; mt < 2; ++mt) {
        int r0 = row0 + wr * 32 + mt * 16 + g;
#pragma unroll
        for (int half = 0; half < 2; ++half) {
            int n = r0 + half * 8;
            if (n < NNODES) {
                float* dst = hout + (size_t)n * DIM;
#pragma unroll
                for (int nt = 0; nt < 8; ++nt) {
                    int col = wc * 64 + nt * 8 + t4 * 2;
                    float2 o;
                    o.x = fmaxf(acc[mt][nt][half * 2 + 0] + bb[nt].x, 0.f);
                    o.y = fmaxf(acc[mt][nt][half * 2 + 1] + bb[nt].y, 0.f);
                    *reinterpret_cast<float2*>(dst + col) = o;
                }
            }
        }
    }
}

// ---------------- DistMult score: one warp per triple ---------------------
__global__ void score_kernel(const float* __restrict__ rel_emb,
                             const int* __restrict__ head,
                             const int* __restrict__ rel,
                             const int* __restrict__ tail,
                             float* __restrict__ out) {
    int t    = (blockIdx.x * blockDim.x + threadIdx.x) >> 5;
    int lane = threadIdx.x & 31;
    if (t >= NTRIP) return;
    const float4 a = reinterpret_cast<const float4*>(
        g_h2 + (size_t)head[t] * DIM)[lane];
    const float4 r = reinterpret_cast<const float4*>(
        rel_emb + (size_t)rel[t] * DIM)[lane];
    const float4 b = reinterpret_cast<const float4*>(
        g_h2 + (size_t)tail[t] * DIM)[lane];
    float s = a.x * r.x * b.x + a.y * r.y * b.y
            + a.z * r.z * b.z + a.w * r.w * b.w;
#pragma unroll
    for (int off = 16; off; off >>= 1)
        s += __shfl_xor_sync(0xFFFFFFFFu, s, off);
    if (lane == 0) out[t] = s;
}

// ---------------- launcher -------------------------------------------------
extern "C" void kernel_launch(void* const* d_in, const int* in_sizes, int n_in,
                              void* d_out, int out_size) {
    const float* emb   = (const float*)d_in[0];
    const float* W0    = (const float*)d_in[1];
    const float* root0 = (const float*)d_in[2];
    const float* b0    = (const float*)d_in[3];
    const float* W1    = (const float*)d_in[4];
    const float* root1 = (const float*)d_in[5];
    const float* b1    = (const float*)d_in[6];
    const float* relE  = (const float*)d_in[7];
    const int*   ei    = (const int*)d_in[8];
    const int*   et    = (const int*)d_in[9];
    const int*   hidx  = (const int*)d_in[10];
    const int*   ridx  = (const int*)d_in[11];
    const int*   tidx  = (const int*)d_in[12];
    float*       out   = (float*)d_out;

    static int smemSet = 0;
    if (!smemSet) {
        cudaFuncSetAttribute(rgcn_layer_fused,
                             cudaFuncAttributeMaxDynamicSharedMemorySize,
                             SMEM_TOT);
        smemSet = 1;
    }

    const int edgeGrid  = (NEDGE + 255) / 256;   // 3125
    const int layerGrid = (NNODES + 127) / 128;  // 391
    const int scoreGrid = (NTRIP * 32 + 255) / 256;

    // weights transpose + tf32 round (once, both layers)
    transpose_w<<<2 * KTOT, 128>>>(W0, root0, W1, root1);

    // ----- CSR build (shared by both layers) -----
    csr_zero<<<1024, 256>>>();
    csr_hist<<<edgeGrid, 256>>>(ei, et);
    csr_bsum<<<NBLK, 1024>>>();
    csr_bscan<<<1, 512>>>();
    csr_off<<<NBLK, 1024>>>();
    csr_fill<<<edgeGrid, 256>>>(ei, et);

    // ----- layer 0 -----
    rgcn_layer_fused<<<layerGrid, 256, SMEM_TOT>>>(emb, 0, /*wt*/0, b0, /*out*/0);
    // ----- layer 1 -----
    rgcn_layer_fused<<<layerGrid, 256, SMEM_TOT>>>(nullptr, 1, /*wt*/1, b1, /*out*/1);

    // ----- DistMult score -----
    score_kernel<<<scoreGrid, 256>>>(relE, hidx, ridx, tidx, out);
}

// round 8
// speedup vs baseline: 1.7101x; 1.7101x over previous
#include <cuda_runtime.h>
#include <cstdint>

// Problem sizes (fixed by the reference)
#define NNODES 50000
#define NREL   8
#define DIM    128
#define NEDGE  800000
#define NTRIP  100000
#define KTOT   1152          // NREL*DIM + DIM (root folded as 9th block)
#define K0LIM  1024          // NREL*DIM
#define NSEG   (NNODES * NREL)          // 400000
#define NBLK   ((NSEG + 1023) / 1024)   // 391

// ---------------- scratch (static device globals; no allocs allowed) -------
__device__ __align__(16) float g_sum[(size_t)NNODES * NREL * DIM]; // 204.8 MB (means)
__device__ __align__(16) float g_h1[(size_t)NNODES * DIM];   // 25.6 MB
__device__ __align__(16) float g_h2[(size_t)NNODES * DIM];   // 25.6 MB
__device__ __align__(16) float g_WT0[(size_t)DIM * KTOT];    // (W0||root0)^T tf32
__device__ __align__(16) float g_WT1[(size_t)DIM * KTOT];    // (W1||root1)^T tf32
__device__ int g_cnt[NSEG];
__device__ int g_off[NSEG];
__device__ int g_fill[NSEG];
__device__ int g_csr[NEDGE];
__device__ int g_bsum[NBLK];
__device__ int g_bbase[NBLK];

// ---------------- W||root transpose + tf32 round --------------------------
__global__ void transpose_w(const float* __restrict__ W0,
                            const float* __restrict__ root0,
                            const float* __restrict__ W1,
                            const float* __restrict__ root1) {
    int b = blockIdx.x;
    int layer = b / KTOT;
    int k = b % KTOT;
    const float* src;
    if (layer == 0)
        src = (k < K0LIM) ? (W0 + (size_t)k * DIM) : (root0 + (size_t)(k - K0LIM) * DIM);
    else
        src = (k < K0LIM) ? (W1 + (size_t)k * DIM) : (root1 + (size_t)(k - K0LIM) * DIM);
    float v = src[threadIdx.x];
    uint32_t t;
    asm("cvt.rna.tf32.f32 %0, %1;" : "=r"(t) : "f"(v));
    float* dst = layer ? g_WT1 : g_WT0;
    dst[(size_t)threadIdx.x * KTOT + k] = __uint_as_float(t);
}

// ---------------- CSR build -----------------------------------------------
__global__ void csr_zero() {
    for (int i = blockIdx.x * blockDim.x + threadIdx.x; i < NSEG;
         i += gridDim.x * blockDim.x) {
        g_cnt[i] = 0;
        g_fill[i] = 0;
    }
}
__global__ void csr_hist(const int* __restrict__ ei,
                         const int* __restrict__ et) {
    int e = blockIdx.x * blockDim.x + threadIdx.x;
    if (e >= NEDGE) return;
    int seg = ei[NEDGE + e] * NREL + et[e];
    atomicAdd(&g_cnt[seg], 1);
}
__global__ void csr_bsum() {  // grid NBLK x 1024
    __shared__ int sh[1024];
    int gid = blockIdx.x * 1024 + threadIdx.x;
    sh[threadIdx.x] = (gid < NSEG) ? g_cnt[gid] : 0;
    __syncthreads();
    for (int s = 512; s > 0; s >>= 1) {
        if (threadIdx.x < s) sh[threadIdx.x] += sh[threadIdx.x + s];
        __syncthreads();
    }
    if (threadIdx.x == 0) g_bsum[blockIdx.x] = sh[0];
}
__global__ void csr_bscan() {  // 1 block x 512
    __shared__ int sh[512];
    int v = (threadIdx.x < NBLK) ? g_bsum[threadIdx.x] : 0;
    sh[threadIdx.x] = v;
    __syncthreads();
    for (int ofs = 1; ofs < 512; ofs <<= 1) {
        int t = (threadIdx.x >= ofs) ? sh[threadIdx.x - ofs] : 0;
        __syncthreads();
        sh[threadIdx.x] += t;
        __syncthreads();
    }
    if (threadIdx.x < NBLK) g_bbase[threadIdx.x] = sh[threadIdx.x] - v;
}
__global__ void csr_off() {  // grid NBLK x 1024
    __shared__ int sh[1024];
    int gid = blockIdx.x * 1024 + threadIdx.x;
    int v = (gid < NSEG) ? g_cnt[gid] : 0;
    sh[threadIdx.x] = v;
    __syncthreads();
    for (int ofs = 1; ofs < 1024; ofs <<= 1) {
        int t = (threadIdx.x >= ofs) ? sh[threadIdx.x - ofs] : 0;
        __syncthreads();
        sh[threadIdx.x] += t;
        __syncthreads();
    }
    if (gid < NSEG) g_off[gid] = g_bbase[blockIdx.x] + sh[threadIdx.x] - v;
}
__global__ void csr_fill(const int* __restrict__ ei,
                         const int* __restrict__ et) {
    int e = blockIdx.x * blockDim.x + threadIdx.x;
    if (e >= NEDGE) return;
    int seg = ei[NEDGE + e] * NREL + et[e];
    int pos = g_off[seg] + atomicAdd(&g_fill[seg], 1);
    g_csr[pos] = ei[e];
}

// ---------------- aggregate: warp per segment, dense mean write -----------
__global__ __launch_bounds__(256) void aggregate_kernel(
    const float* __restrict__ hin_ext, int useG) {
    int w    = (blockIdx.x * blockDim.x + threadIdx.x) >> 5;
    int lane = threadIdx.x & 31;
    if (w >= NSEG) return;
    const float* __restrict__ h = useG ? g_h1 : hin_ext;

    int beg = g_off[w];
    int c   = g_cnt[w];
    float4 acc = make_float4(0.f, 0.f, 0.f, 0.f);
    for (int base = 0; base < c; base += 4) {
        int s[4];
#pragma unroll
        for (int j = 0; j < 4; ++j)
            s[j] = (base + j < c) ? g_csr[beg + base + j] : -1;
#pragma unroll
        for (int j = 0; j < 4; ++j) {
            if (s[j] >= 0) {
                float4 t = reinterpret_cast<const float4*>(
                    h + (size_t)s[j] * DIM)[lane];
                acc.x += t.x; acc.y += t.y; acc.z += t.z; acc.w += t.w;
            }
        }
    }
    float inv = 1.0f / (float)max(c, 1);
    acc.x *= inv; acc.y *= inv; acc.z *= inv; acc.w *= inv;
    reinterpret_cast<float4*>(g_sum + (size_t)w * DIM)[lane] = acc;
}

// ---------------- tf32 mma.sync RGCN layer GEMM ---------------------------
// out[n,:] = relu( [g_sum(means) || hin[n,:]] @ Wcat + bias )
// BM=128, BN=128, BK=32 double-buffered. 8 warps 4x2, warp tile 32x64.
#define KCH     32
#define NCHUNK  (KTOT / KCH)            // 36
#define LDP     36
#define BUF_F   (2 * 128 * LDP)         // 9216 floats per buffer (A+B)
#define SMEM_TOT (2 * BUF_F * 4)        // 73728 B

__device__ __forceinline__ void mma_tf32(float* c, const uint32_t* a,
                                         const uint32_t* b) {
    asm volatile(
        "mma.sync.aligned.m16n8k8.row.col.f32.tf32.tf32.f32 "
        "{%0,%1,%2,%3}, {%4,%5,%6,%7}, {%8,%9}, {%0,%1,%2,%3};"
        : "+f"(c[0]), "+f"(c[1]), "+f"(c[2]), "+f"(c[3])
        : "r"(a[0]), "r"(a[1]), "r"(a[2]), "r"(a[3]), "r"(b[0]), "r"(b[1]));
}

__global__ __launch_bounds__(256, 2) void rgcn_gemm_mma(
    const float* __restrict__ hin_ext, int useGin, int wtSel,
    const float* __restrict__ bias, int outSel)
{
    extern __shared__ float smemf[];
    const int tid  = threadIdx.x;
    const int wid  = tid >> 5;
    const int lane = tid & 31;
    const int g    = lane >> 2;
    const int t4   = lane & 3;
    const int wr   = wid & 3;        // warp row (M: 4 x 32)
    const int wc   = wid >> 2;       // warp col (N: 2 x 64)
    const int row0 = blockIdx.x * 128;

    const float* __restrict__ hin = useGin ? g_h1 : hin_ext;
    const float* __restrict__ WT  = wtSel ? g_WT1 : g_WT0;
    float* __restrict__ hout = outSel ? g_h2 : g_h1;

    float acc[2][8][4];
#pragma unroll
    for (int mt = 0; mt < 2; ++mt)
#pragma unroll
        for (int nt = 0; nt < 8; ++nt)
#pragma unroll
            for (int j = 0; j < 4; ++j) acc[mt][nt][j] = 0.f;

    float4 va[4], vb[4];

    auto load_regs = [&](int c) {
        const int k0 = c * KCH;
#pragma unroll
        for (int it = 0; it < 4; ++it) {
            int idx = tid + it * 256;
            int m = idx >> 3, q = idx & 7;
            int n = row0 + m;
            float4 v = make_float4(0.f, 0.f, 0.f, 0.f);
            if (n < NNODES) {
                if (k0 < K0LIM)
                    v = *reinterpret_cast<const float4*>(
                        g_sum + (size_t)n * K0LIM + k0 + q * 4);
                else
                    v = *reinterpret_cast<const float4*>(
                        hin + (size_t)n * DIM + (k0 - K0LIM) + q * 4);
            }
            va[it] = v;
            vb[it] = *reinterpret_cast<const float4*>(
                WT + (size_t)m * KTOT + k0 + q * 4);
        }
    };

    auto store_smem = [&](int buf) {
        float* smA = smemf + buf * BUF_F;
        float* smB = smA + 128 * LDP;
#pragma unroll
        for (int it = 0; it < 4; ++it) {
            int idx = tid + it * 256;
            int m = idx >> 3, q = idx & 7;
            float4 v = va[it];
            uint4 r;
            asm("cvt.rna.tf32.f32 %0, %1;" : "=r"(r.x) : "f"(v.x));
            asm("cvt.rna.tf32.f32 %0, %1;" : "=r"(r.y) : "f"(v.y));
            asm("cvt.rna.tf32.f32 %0, %1;" : "=r"(r.z) : "f"(v.z));
            asm("cvt.rna.tf32.f32 %0, %1;" : "=r"(r.w) : "f"(v.w));
            *reinterpret_cast<uint4*>(smA + m * LDP + q * 4) = r;
            *reinterpret_cast<float4*>(smB + m * LDP + q * 4) = vb[it];
        }
    };

    auto compute = [&](int buf) {
        const float* smA = smemf + buf * BUF_F;
        const float* smB = smA + 128 * LDP;
#pragma unroll
        for (int ks = 0; ks < 4; ++ks) {
            const int kk = ks * 8;
            uint32_t a[2][4], b[8][2];
#pragma unroll
            for (int mt = 0; mt < 2; ++mt) {
                int r0 = wr * 32 + mt * 16 + g;
                a[mt][0] = __float_as_uint(smA[(r0)     * LDP + kk + t4]);
                a[mt][1] = __float_as_uint(smA[(r0 + 8) * LDP + kk + t4]);
                a[mt][2] = __float_as_uint(smA[(r0)     * LDP + kk + t4 + 4]);
                a[mt][3] = __float_as_uint(smA[(r0 + 8) * LDP + kk + t4 + 4]);
            }
#pragma unroll
            for (int nt = 0; nt < 8; ++nt) {
                int nn = wc * 64 + nt * 8 + g;
                b[nt][0] = __float_as_uint(smB[nn * LDP + kk + t4]);
                b[nt][1] = __float_as_uint(smB[nn * LDP + kk + t4 + 4]);
            }
#pragma unroll
            for (int mt = 0; mt < 2; ++mt)
#pragma unroll
                for (int nt = 0; nt < 8; ++nt)
                    mma_tf32(acc[mt][nt], a[mt], b[nt]);
        }
    };

    load_regs(0);
    store_smem(0);
    __syncthreads();
    for (int c = 0; c < NCHUNK; ++c) {
        if (c + 1 < NCHUNK) load_regs(c + 1);
        compute(c & 1);
        if (c + 1 < NCHUNK) store_smem((c + 1) & 1);
        __syncthreads();
    }

    // ---- epilogue: bias + relu ----
    float2 bb[8];
#pragma unroll
    for (int nt = 0; nt < 8; ++nt) {
        int col = wc * 64 + nt * 8 + t4 * 2;
        bb[nt].x = __ldg(bias + col);
        bb[nt].y = __ldg(bias + col + 1);
    }
#pragma unroll
    for (int mt = 0; mt < 2; ++mt) {
        int r0 = row0 + wr * 32 + mt * 16 + g;
#pragma unroll
        for (int half = 0; half < 2; ++half) {
            int n = r0 + half * 8;
            if (n < NNODES) {
                float* dst = hout + (size_t)n * DIM;
#pragma unroll
                for (int nt = 0; nt < 8; ++nt) {
                    int col = wc * 64 + nt * 8 + t4 * 2;
                    float2 o;
                    o.x = fmaxf(acc[mt][nt][half * 2 + 0] + bb[nt].x, 0.f);
                    o.y = fmaxf(acc[mt][nt][half * 2 + 1] + bb[nt].y, 0.f);
                    *reinterpret_cast<float2*>(dst + col) = o;
                }
            }
        }
    }
}

// ---------------- DistMult score: one warp per triple ---------------------
__global__ void score_kernel(const float* __restrict__ rel_emb,
                             const int* __restrict__ head,
                             const int* __restrict__ rel,
                             const int* __restrict__ tail,
                             float* __restrict__ out) {
    int t    = (blockIdx.x * blockDim.x + threadIdx.x) >> 5;
    int lane = threadIdx.x & 31;
    if (t >= NTRIP) return;
    const float4 a = reinterpret_cast<const float4*>(
        g_h2 + (size_t)head[t] * DIM)[lane];
    const float4 r = reinterpret_cast<const float4*>(
        rel_emb + (size_t)rel[t] * DIM)[lane];
    const float4 b = reinterpret_cast<const float4*>(
        g_h2 + (size_t)tail[t] * DIM)[lane];
    float s = a.x * r.x * b.x + a.y * r.y * b.y
            + a.z * r.z * b.z + a.w * r.w * b.w;
#pragma unroll
    for (int off = 16; off; off >>= 1)
        s += __shfl_xor_sync(0xFFFFFFFFu, s, off);
    if (lane == 0) out[t] = s;
}

// ---------------- launcher -------------------------------------------------
extern "C" void kernel_launch(void* const* d_in, const int* in_sizes, int n_in,
                              void* d_out, int out_size) {
    const float* emb   = (const float*)d_in[0];
    const float* W0    = (const float*)d_in[1];
    const float* root0 = (const float*)d_in[2];
    const float* b0    = (const float*)d_in[3];
    const float* W1    = (const float*)d_in[4];
    const float* root1 = (const float*)d_in[5];
    const float* b1    = (const float*)d_in[6];
    const float* relE  = (const float*)d_in[7];
    const int*   ei    = (const int*)d_in[8];
    const int*   et    = (const int*)d_in[9];
    const int*   hidx  = (const int*)d_in[10];
    const int*   ridx  = (const int*)d_in[11];
    const int*   tidx  = (const int*)d_in[12];
    float*       out   = (float*)d_out;

    static int smemSet = 0;
    if (!smemSet) {
        cudaFuncSetAttribute(rgcn_gemm_mma,
                             cudaFuncAttributeMaxDynamicSharedMemorySize,
                             SMEM_TOT);
        smemSet = 1;
    }

    const int edgeGrid  = (NEDGE + 255) / 256;          // 3125
    const int aggGrid   = (NSEG * 32 + 255) / 256;      // 50000
    const int gemmGrid  = (NNODES + 127) / 128;         // 391
    const int scoreGrid = (NTRIP * 32 + 255) / 256;     // 12500

    // weights transpose + tf32 round (once, both layers)
    transpose_w<<<2 * KTOT, 128>>>(W0, root0, W1, root1);

    // ----- CSR build (shared by both layers) -----
    csr_zero<<<1024, 256>>>();
    csr_hist<<<edgeGrid, 256>>>(ei, et);
    csr_bsum<<<NBLK, 1024>>>();
    csr_bscan<<<1, 512>>>();
    csr_off<<<NBLK, 1024>>>();
    csr_fill<<<edgeGrid, 256>>>(ei, et);

    // ----- layer 0 -----
    aggregate_kernel<<<aggGrid, 256>>>(emb, 0);
    rgcn_gemm_mma<<<gemmGrid, 256, SMEM_TOT>>>(emb, 0, /*wt*/0, b0, /*out*/0);

    // ----- layer 1 -----
    aggregate_kernel<<<aggGrid, 256>>>(nullptr, 1);
    rgcn_gemm_mma<<<gemmGrid, 256, SMEM_TOT>>>(nullptr, 1, /*wt*/1, b1, /*out*/1);

    // ----- DistMult score -----
    score_kernel<<<scoreGrid, 256>>>(relE, hidx, ridx, tidx, out);
}

// round 9
// speedup vs baseline: 1.7807x; 1.0413x over previous
#include <cuda_runtime.h>
#include <cstdint>

// Problem sizes (fixed by the reference)
#define NNODES 50000
#define NREL   8
#define DIM    128
#define NEDGE  800000
#define NTRIP  100000
#define KTOT   1152          // NREL*DIM + DIM (root folded as 9th block)
#define K0LIM  1024          // NREL*DIM
#define NSEG   (NNODES * NREL)          // 400000
#define NBLK   ((NSEG + 1023) / 1024)   // 391

// ---------------- scratch (static device globals; no allocs allowed) -------
__device__ __align__(16) float g_sum[(size_t)NNODES * NREL * DIM]; // 204.8 MB (tf32 means)
__device__ __align__(16) float g_h1[(size_t)NNODES * DIM];   // 25.6 MB
__device__ __align__(16) float g_h2[(size_t)NNODES * DIM];   // 25.6 MB
__device__ __align__(16) float g_WT0[(size_t)DIM * KTOT];    // (W0||root0)^T tf32
__device__ __align__(16) float g_WT1[(size_t)DIM * KTOT];    // (W1||root1)^T tf32
__device__ int g_cnt[NSEG];
__device__ int g_off[NSEG];
__device__ int g_fill[NSEG];
__device__ int g_csr[NEDGE];
__device__ int g_bsum[NBLK];
__device__ int g_bbase[NBLK];

__device__ __forceinline__ uint32_t to_tf32(float f) {
    uint32_t t;
    asm("cvt.rna.tf32.f32 %0, %1;" : "=r"(t) : "f"(f));
    return t;
}
__device__ __forceinline__ uint32_t smem_u32(const void* p) {
    uint32_t a;
    asm("{ .reg .u64 t; cvta.to.shared.u64 t, %1; cvt.u32.u64 %0, t; }"
        : "=r"(a) : "l"(p));
    return a;
}
__device__ __forceinline__ void cp16(uint32_t dst, const void* src, bool pred) {
    int sz = pred ? 16 : 0;
    asm volatile("cp.async.cg.shared.global [%0], [%1], 16, %2;"
                 :: "r"(dst), "l"(src), "r"(sz) : "memory");
}

// ---------------- W||root transpose + tf32 round --------------------------
__global__ void transpose_w(const float* __restrict__ W0,
                            const float* __restrict__ root0,
                            const float* __restrict__ W1,
                            const float* __restrict__ root1) {
    int b = blockIdx.x;
    int layer = b / KTOT;
    int k = b % KTOT;
    const float* src;
    if (layer == 0)
        src = (k < K0LIM) ? (W0 + (size_t)k * DIM) : (root0 + (size_t)(k - K0LIM) * DIM);
    else
        src = (k < K0LIM) ? (W1 + (size_t)k * DIM) : (root1 + (size_t)(k - K0LIM) * DIM);
    float v = src[threadIdx.x];
    float* dst = layer ? g_WT1 : g_WT0;
    dst[(size_t)threadIdx.x * KTOT + k] = __uint_as_float(to_tf32(v));
}

// ---------------- CSR build -----------------------------------------------
__global__ void csr_zero() {
    for (int i = blockIdx.x * blockDim.x + threadIdx.x; i < NSEG;
         i += gridDim.x * blockDim.x) {
        g_cnt[i] = 0;
        g_fill[i] = 0;
    }
}
__global__ void csr_hist(const int* __restrict__ ei,
                         const int* __restrict__ et) {
    int e = blockIdx.x * blockDim.x + threadIdx.x;
    if (e >= NEDGE) return;
    int seg = ei[NEDGE + e] * NREL + et[e];
    atomicAdd(&g_cnt[seg], 1);
}
__global__ void csr_bsum() {  // grid NBLK x 1024
    __shared__ int sh[1024];
    int gid = blockIdx.x * 1024 + threadIdx.x;
    sh[threadIdx.x] = (gid < NSEG) ? g_cnt[gid] : 0;
    __syncthreads();
    for (int s = 512; s > 0; s >>= 1) {
        if (threadIdx.x < s) sh[threadIdx.x] += sh[threadIdx.x + s];
        __syncthreads();
    }
    if (threadIdx.x == 0) g_bsum[blockIdx.x] = sh[0];
}
__global__ void csr_bscan() {  // 1 block x 512
    __shared__ int sh[512];
    int v = (threadIdx.x < NBLK) ? g_bsum[threadIdx.x] : 0;
    sh[threadIdx.x] = v;
    __syncthreads();
    for (int ofs = 1; ofs < 512; ofs <<= 1) {
        int t = (threadIdx.x >= ofs) ? sh[threadIdx.x - ofs] : 0;
        __syncthreads();
        sh[threadIdx.x] += t;
        __syncthreads();
    }
    if (threadIdx.x < NBLK) g_bbase[threadIdx.x] = sh[threadIdx.x] - v;
}
__global__ void csr_off() {  // grid NBLK x 1024
    __shared__ int sh[1024];
    int gid = blockIdx.x * 1024 + threadIdx.x;
    int v = (gid < NSEG) ? g_cnt[gid] : 0;
    sh[threadIdx.x] = v;
    __syncthreads();
    for (int ofs = 1; ofs < 1024; ofs <<= 1) {
        int t = (threadIdx.x >= ofs) ? sh[threadIdx.x - ofs] : 0;
        __syncthreads();
        sh[threadIdx.x] += t;
        __syncthreads();
    }
    if (gid < NSEG) g_off[gid] = g_bbase[blockIdx.x] + sh[threadIdx.x] - v;
}
__global__ void csr_fill(const int* __restrict__ ei,
                         const int* __restrict__ et) {
    int e = blockIdx.x * blockDim.x + threadIdx.x;
    if (e >= NEDGE) return;
    int seg = ei[NEDGE + e] * NREL + et[e];
    int pos = g_off[seg] + atomicAdd(&g_fill[seg], 1);
    g_csr[pos] = ei[e];
}

// ---------------- aggregate: warp per segment, tf32 mean, streaming write --
__global__ __launch_bounds__(256) void aggregate_kernel(
    const float* __restrict__ hin_ext, int useG) {
    int w    = (blockIdx.x * blockDim.x + threadIdx.x) >> 5;
    int lane = threadIdx.x & 31;
    if (w >= NSEG) return;
    const float* __restrict__ h = useG ? g_h1 : hin_ext;

    int beg = g_off[w];
    int c   = g_cnt[w];
    float4 acc = make_float4(0.f, 0.f, 0.f, 0.f);
    for (int base = 0; base < c; base += 4) {
        int s[4];
#pragma unroll
        for (int j = 0; j < 4; ++j)
            s[j] = (base + j < c) ? g_csr[beg + base + j] : -1;
#pragma unroll
        for (int j = 0; j < 4; ++j) {
            if (s[j] >= 0) {
                float4 t = reinterpret_cast<const float4*>(
                    h + (size_t)s[j] * DIM)[lane];
                acc.x += t.x; acc.y += t.y; acc.z += t.z; acc.w += t.w;
            }
        }
    }
    float inv = 1.0f / (float)max(c, 1);
    uint4 r;
    r.x = to_tf32(acc.x * inv);
    r.y = to_tf32(acc.y * inv);
    r.z = to_tf32(acc.z * inv);
    r.w = to_tf32(acc.w * inv);
    // streaming store: keep h resident in L2, g_sum is a one-shot stream
    __stcs(reinterpret_cast<uint4*>(g_sum + (size_t)w * DIM) + lane, r);
}

// ---------------- tf32 mma.sync RGCN layer GEMM (cp.async pipeline) --------
// out[n,:] = relu( [g_sum(tf32 means) || hin[n,:]] @ Wcat + bias )
// BM=128, BN=128, BK=32, 3-stage cp.async. 8 warps 4x2, warp tile 32x64.
#define KCH     32
#define NCHUNK  (KTOT / KCH)            // 36
#define LDP     36
#define BUF_F   (2 * 128 * LDP)         // 9216 floats per stage (A+B)
#define NSTAGE  3
#define SMEM_TOT (NSTAGE * BUF_F * 4)   // 110592 B

__device__ __forceinline__ void mma_tf32(float* c, const uint32_t* a,
                                         const uint32_t* b) {
    asm volatile(
        "mma.sync.aligned.m16n8k8.row.col.f32.tf32.tf32.f32 "
        "{%0,%1,%2,%3}, {%4,%5,%6,%7}, {%8,%9}, {%0,%1,%2,%3};"
        : "+f"(c[0]), "+f"(c[1]), "+f"(c[2]), "+f"(c[3])
        : "r"(a[0]), "r"(a[1]), "r"(a[2]), "r"(a[3]), "r"(b[0]), "r"(b[1]));
}

__global__ __launch_bounds__(256, 2) void rgcn_gemm_mma(
    const float* __restrict__ hin_ext, int useGin, int wtSel,
    const float* __restrict__ bias, int outSel)
{
    extern __shared__ float smemf[];
    const uint32_t smemBase = smem_u32(smemf);
    const int tid  = threadIdx.x;
    const int wid  = tid >> 5;
    const int lane = tid & 31;
    const int g    = lane >> 2;
    const int t4   = lane & 3;
    const int wr   = wid & 3;        // warp row (M: 4 x 32)
    const int wc   = wid >> 2;       // warp col (N: 2 x 64)
    const int row0 = blockIdx.x * 128;

    const float* __restrict__ hin = useGin ? g_h1 : hin_ext;
    const float* __restrict__ WT  = wtSel ? g_WT1 : g_WT0;
    float* __restrict__ hout = outSel ? g_h2 : g_h1;

    float acc[2][8][4];
#pragma unroll
    for (int mt = 0; mt < 2; ++mt)
#pragma unroll
        for (int nt = 0; nt < 8; ++nt)
#pragma unroll
            for (int j = 0; j < 4; ++j) acc[mt][nt][j] = 0.f;

    // ---- issue cp.async loads for chunk c into stage buf ----
    auto issue = [&](int buf, int c) {
        const int k0 = c * KCH;
        const bool isSum = (k0 < K0LIM);
        uint32_t aBase = smemBase + (uint32_t)(buf * BUF_F) * 4u;
        uint32_t bBase = aBase + 128u * LDP * 4u;
#pragma unroll
        for (int it = 0; it < 4; ++it) {
            int idx = tid + it * 256;
            int m = idx >> 3, q = idx & 7;
            int n = row0 + m;
            bool ok = (n < NNODES);
            int nc = ok ? n : (NNODES - 1);
            const float* srcA = isSum
                ? (g_sum + (size_t)nc * K0LIM + k0 + q * 4)
                : (hin + (size_t)nc * DIM + (k0 - K0LIM) + q * 4);
            uint32_t off = (uint32_t)(m * LDP + q * 4) * 4u;
            cp16(aBase + off, srcA, ok);
            cp16(bBase + off, WT + (size_t)m * KTOT + k0 + q * 4, true);
        }
        asm volatile("cp.async.commit_group;" ::: "memory");
    };

    // ---- compute one k-chunk from stage buf ----
    auto compute = [&](int buf, bool isRoot) {
        const float* smA = smemf + buf * BUF_F;
        const float* smB = smA + 128 * LDP;
#pragma unroll
        for (int ks = 0; ks < 4; ++ks) {
            const int kk = ks * 8;
            uint32_t a[2][4], b[8][2];
#pragma unroll
            for (int mt = 0; mt < 2; ++mt) {
                int r0 = wr * 32 + mt * 16 + g;
                a[mt][0] = __float_as_uint(smA[(r0)     * LDP + kk + t4]);
                a[mt][1] = __float_as_uint(smA[(r0 + 8) * LDP + kk + t4]);
                a[mt][2] = __float_as_uint(smA[(r0)     * LDP + kk + t4 + 4]);
                a[mt][3] = __float_as_uint(smA[(r0 + 8) * LDP + kk + t4 + 4]);
                if (isRoot) {
#pragma unroll
                    for (int j = 0; j < 4; ++j)
                        a[mt][j] = to_tf32(__uint_as_float(a[mt][j]));
                }
            }
#pragma unroll
            for (int nt = 0; nt < 8; ++nt) {
                int nn = wc * 64 + nt * 8 + g;
                b[nt][0] = __float_as_uint(smB[nn * LDP + kk + t4]);
                b[nt][1] = __float_as_uint(smB[nn * LDP + kk + t4 + 4]);
            }
#pragma unroll
            for (int mt = 0; mt < 2; ++mt)
#pragma unroll
                for (int nt = 0; nt < 8; ++nt)
                    mma_tf32(acc[mt][nt], a[mt], b[nt]);
        }
    };

    // ---- 3-stage pipeline ----
    issue(0, 0);
    issue(1, 1);
    for (int c = 0; c < NCHUNK; ++c) {
        if (c + 2 < NCHUNK) {
            issue((c + 2) % NSTAGE, c + 2);
            asm volatile("cp.async.wait_group 2;" ::: "memory");
        } else if (c + 1 < NCHUNK) {
            asm volatile("cp.async.wait_group 1;" ::: "memory");
        } else {
            asm volatile("cp.async.wait_group 0;" ::: "memory");
        }
        __syncthreads();
        compute(c % NSTAGE, c * KCH >= K0LIM);
        __syncthreads();
    }

    // ---- epilogue: bias + relu ----
    float2 bb[8];
#pragma unroll
    for (int nt = 0; nt < 8; ++nt) {
        int col = wc * 64 + nt * 8 + t4 * 2;
        bb[nt].x = __ldg(bias + col);
        bb[nt].y = __ldg(bias + col + 1);
    }
#pragma unroll
    for (int mt = 0; mt < 2; ++mt) {
        int r0 = row0 + wr * 32 + mt * 16 + g;
#pragma unroll
        for (int half = 0; half < 2; ++half) {
            int n = r0 + half * 8;
            if (n < NNODES) {
                float* dst = hout + (size_t)n * DIM;
#pragma unroll
                for (int nt = 0; nt < 8; ++nt) {
                    int col = wc * 64 + nt * 8 + t4 * 2;
                    float2 o;
                    o.x = fmaxf(acc[mt][nt][half * 2 + 0] + bb[nt].x, 0.f);
                    o.y = fmaxf(acc[mt][nt][half * 2 + 1] + bb[nt].y, 0.f);
                    *reinterpret_cast<float2*>(dst + col) = o;
                }
            }
        }
    }
}

// ---------------- DistMult score: one warp per triple ---------------------
__global__ void score_kernel(const float* __restrict__ rel_emb,
                             const int* __restrict__ head,
                             const int* __restrict__ rel,
                             const int* __restrict__ tail,
                             float* __restrict__ out) {
    int t    = (blockIdx.x * blockDim.x + threadIdx.x) >> 5;
    int lane = threadIdx.x & 31;
    if (t >= NTRIP) return;
    const float4 a = reinterpret_cast<const float4*>(
        g_h2 + (size_t)head[t] * DIM)[lane];
    const float4 r = reinterpret_cast<const float4*>(
        rel_emb + (size_t)rel[t] * DIM)[lane];
    const float4 b = reinterpret_cast<const float4*>(
        g_h2 + (size_t)tail[t] * DIM)[lane];
    float s = a.x * r.x * b.x + a.y * r.y * b.y
            + a.z * r.z * b.z + a.w * r.w * b.w;
#pragma unroll
    for (int off = 16; off; off >>= 1)
        s += __shfl_xor_sync(0xFFFFFFFFu, s, off);
    if (lane == 0) out[t] = s;
}

// ---------------- launcher -------------------------------------------------
extern "C" void kernel_launch(void* const* d_in, const int* in_sizes, int n_in,
                              void* d_out, int out_size) {
    const float* emb   = (const float*)d_in[0];
    const float* W0    = (const float*)d_in[1];
    const float* root0 = (const float*)d_in[2];
    const float* b0    = (const float*)d_in[3];
    const float* W1    = (const float*)d_in[4];
    const float* root1 = (const float*)d_in[5];
    const float* b1    = (const float*)d_in[6];
    const float* relE  = (const float*)d_in[7];
    const int*   ei    = (const int*)d_in[8];
    const int*   et    = (const int*)d_in[9];
    const int*   hidx  = (const int*)d_in[10];
    const int*   ridx  = (const int*)d_in[11];
    const int*   tidx  = (const int*)d_in[12];
    float*       out   = (float*)d_out;

    static int smemSet = 0;
    if (!smemSet) {
        cudaFuncSetAttribute(rgcn_gemm_mma,
                             cudaFuncAttributeMaxDynamicSharedMemorySize,
                             SMEM_TOT);
        smemSet = 1;
    }

    const int edgeGrid  = (NEDGE + 255) / 256;          // 3125
    const int aggGrid   = (NSEG * 32 + 255) / 256;      // 50000
    const int gemmGrid  = (NNODES + 127) / 128;         // 391
    const int scoreGrid = (NTRIP * 32 + 255) / 256;     // 12500

    // weights transpose + tf32 round (once, both layers)
    transpose_w<<<2 * KTOT, 128>>>(W0, root0, W1, root1);

    // ----- CSR build (shared by both layers) -----
    csr_zero<<<1024, 256>>>();
    csr_hist<<<edgeGrid, 256>>>(ei, et);
    csr_bsum<<<NBLK, 1024>>>();
    csr_bscan<<<1, 512>>>();
    csr_off<<<NBLK, 1024>>>();
    csr_fill<<<edgeGrid, 256>>>(ei, et);

    // ----- layer 0 -----
    aggregate_kernel<<<aggGrid, 256>>>(emb, 0);
    rgcn_gemm_mma<<<gemmGrid, 256, SMEM_TOT>>>(emb, 0, /*wt*/0, b0, /*out*/0);

    // ----- layer 1 -----
    aggregate_kernel<<<aggGrid, 256>>>(nullptr, 1);
    rgcn_gemm_mma<<<gemmGrid, 256, SMEM_TOT>>>(nullptr, 1, /*wt*/1, b1, /*out*/1);

    // ----- DistMult score -----
    score_kernel<<<scoreGrid, 256>>>(relE, hidx, ridx, tidx, out);
}

// round 10
// speedup vs baseline: 2.5451x; 1.4292x over previous
#include <cuda_runtime.h>
#include <cuda_fp16.h>
#include <cstdint>

// Problem sizes (fixed by the reference)
#define NNODES 50000
#define NREL   8
#define DIM    128
#define NEDGE  800000
#define NTRIP  100000
#define KTOT   1152          // NREL*DIM + DIM (root folded as 9th block)
#define K0LIM  1024          // NREL*DIM
#define NSEG   (NNODES * NREL)          // 400000
#define NBLK   ((NSEG + 1023) / 1024)   // 391

// ---------------- scratch (static device globals; no allocs allowed) -------
__device__ __align__(16) __half g_sum16[(size_t)NSEG * DIM];     // 102.4 MB fp16 means
__device__ __align__(16) __half g_e16[(size_t)NNODES * DIM];     // 12.8 MB emb fp16
__device__ __align__(16) __half g_h116[(size_t)NNODES * DIM];    // 12.8 MB
__device__ __align__(16) __half g_h216[(size_t)NNODES * DIM];    // 12.8 MB
__device__ __align__(16) __half g_WT016[(size_t)DIM * KTOT];     // (W0||root0)^T fp16
__device__ __align__(16) __half g_WT116[(size_t)DIM * KTOT];
__device__ int g_cnt[NSEG];
__device__ int g_off[NSEG];
__device__ int g_fill[NSEG];
__device__ int g_csr[NEDGE];
__device__ int g_bsum[NBLK];
__device__ int g_bbase[NBLK];

__device__ __forceinline__ uint32_t smem_u32(const void* p) {
    uint32_t a;
    asm("{ .reg .u64 t; cvta.to.shared.u64 t, %1; cvt.u32.u64 %0, t; }"
        : "=r"(a) : "l"(p));
    return a;
}
__device__ __forceinline__ void cp16(uint32_t dst, const void* src, bool pred) {
    int sz = pred ? 16 : 0;
    asm volatile("cp.async.cg.shared.global [%0], [%1], 16, %2;"
                 :: "r"(dst), "l"(src), "r"(sz) : "memory");
}

// ---------------- emb -> fp16 ----------------------------------------------
__global__ void conv_emb(const float* __restrict__ emb) {
    const size_t n4 = (size_t)NNODES * DIM / 4;
    for (size_t i = (size_t)blockIdx.x * blockDim.x + threadIdx.x;
         i < n4; i += (size_t)gridDim.x * blockDim.x) {
        float4 v = reinterpret_cast<const float4*>(emb)[i];
        __half2 lo = __floats2half2_rn(v.x, v.y);
        __half2 hi = __floats2half2_rn(v.z, v.w);
        uint2 o;
        o.x = *reinterpret_cast<uint32_t*>(&lo);
        o.y = *reinterpret_cast<uint32_t*>(&hi);
        reinterpret_cast<uint2*>(g_e16)[i] = o;
    }
}

// ---------------- W||root transpose -> fp16 --------------------------------
__global__ void transpose_w(const float* __restrict__ W0,
                            const float* __restrict__ root0,
                            const float* __restrict__ W1,
                            const float* __restrict__ root1) {
    int b = blockIdx.x;
    int layer = b / KTOT;
    int k = b % KTOT;
    const float* src;
    if (layer == 0)
        src = (k < K0LIM) ? (W0 + (size_t)k * DIM) : (root0 + (size_t)(k - K0LIM) * DIM);
    else
        src = (k < K0LIM) ? (W1 + (size_t)k * DIM) : (root1 + (size_t)(k - K0LIM) * DIM);
    float v = src[threadIdx.x];
    __half* dst = layer ? g_WT116 : g_WT016;
    dst[(size_t)threadIdx.x * KTOT + k] = __float2half_rn(v);
}

// ---------------- CSR build -----------------------------------------------
__global__ void csr_zero() {
    for (int i = blockIdx.x * blockDim.x + threadIdx.x; i < NSEG;
         i += gridDim.x * blockDim.x) {
        g_cnt[i] = 0;
        g_fill[i] = 0;
    }
}
__global__ void csr_hist(const int* __restrict__ ei,
                         const int* __restrict__ et) {
    int e = blockIdx.x * blockDim.x + threadIdx.x;
    if (e >= NEDGE) return;
    int seg = ei[NEDGE + e] * NREL + et[e];
    atomicAdd(&g_cnt[seg], 1);
}
__global__ void csr_bsum() {  // grid NBLK x 1024
    __shared__ int sh[1024];
    int gid = blockIdx.x * 1024 + threadIdx.x;
    sh[threadIdx.x] = (gid < NSEG) ? g_cnt[gid] : 0;
    __syncthreads();
    for (int s = 512; s > 0; s >>= 1) {
        if (threadIdx.x < s) sh[threadIdx.x] += sh[threadIdx.x + s];
        __syncthreads();
    }
    if (threadIdx.x == 0) g_bsum[blockIdx.x] = sh[0];
}
__global__ void csr_bscan() {  // 1 block x 512
    __shared__ int sh[512];
    int v = (threadIdx.x < NBLK) ? g_bsum[threadIdx.x] : 0;
    sh[threadIdx.x] = v;
    __syncthreads();
    for (int ofs = 1; ofs < 512; ofs <<= 1) {
        int t = (threadIdx.x >= ofs) ? sh[threadIdx.x - ofs] : 0;
        __syncthreads();
        sh[threadIdx.x] += t;
        __syncthreads();
    }
    if (threadIdx.x < NBLK) g_bbase[threadIdx.x] = sh[threadIdx.x] - v;
}
__global__ void csr_off() {  // grid NBLK x 1024
    __shared__ int sh[1024];
    int gid = blockIdx.x * 1024 + threadIdx.x;
    int v = (gid < NSEG) ? g_cnt[gid] : 0;
    sh[threadIdx.x] = v;
    __syncthreads();
    for (int ofs = 1; ofs < 1024; ofs <<= 1) {
        int t = (threadIdx.x >= ofs) ? sh[threadIdx.x - ofs] : 0;
        __syncthreads();
        sh[threadIdx.x] += t;
        __syncthreads();
    }
    if (gid < NSEG) g_off[gid] = g_bbase[blockIdx.x] + sh[threadIdx.x] - v;
}
__global__ void csr_fill(const int* __restrict__ ei,
                         const int* __restrict__ et) {
    int e = blockIdx.x * blockDim.x + threadIdx.x;
    if (e >= NEDGE) return;
    int seg = ei[NEDGE + e] * NREL + et[e];
    int pos = g_off[seg] + atomicAdd(&g_fill[seg], 1);
    g_csr[pos] = ei[e];
}

// ---------------- aggregate: warp per segment, fp16 in/out -----------------
__global__ __launch_bounds__(256) void aggregate_kernel(int useG) {
    int w    = (blockIdx.x * blockDim.x + threadIdx.x) >> 5;
    int lane = threadIdx.x & 31;
    if (w >= NSEG) return;
    const __half* __restrict__ h = useG ? g_h116 : g_e16;

    int beg = g_off[w];
    int c   = g_cnt[w];
    float4 acc = make_float4(0.f, 0.f, 0.f, 0.f);
    for (int base = 0; base < c; base += 4) {
        int s[4];
#pragma unroll
        for (int j = 0; j < 4; ++j)
            s[j] = (base + j < c) ? g_csr[beg + base + j] : -1;
#pragma unroll
        for (int j = 0; j < 4; ++j) {
            if (s[j] >= 0) {
                uint2 t = reinterpret_cast<const uint2*>(
                    h + (size_t)s[j] * DIM)[lane];
                float2 f0 = __half22float2(*reinterpret_cast<__half2*>(&t.x));
                float2 f1 = __half22float2(*reinterpret_cast<__half2*>(&t.y));
                acc.x += f0.x; acc.y += f0.y; acc.z += f1.x; acc.w += f1.y;
            }
        }
    }
    float inv = 1.0f / (float)max(c, 1);
    __half2 o0 = __floats2half2_rn(acc.x * inv, acc.y * inv);
    __half2 o1 = __floats2half2_rn(acc.z * inv, acc.w * inv);
    uint2 r;
    r.x = *reinterpret_cast<uint32_t*>(&o0);
    r.y = *reinterpret_cast<uint32_t*>(&o1);
    // streaming store: keep h resident in L2
    asm volatile("st.global.cs.v2.u32 [%0], {%1,%2};"
                 :: "l"(reinterpret_cast<uint2*>(g_sum16 + (size_t)w * DIM) + lane),
                    "r"(r.x), "r"(r.y) : "memory");
}

// ---------------- fp16 mma.sync RGCN layer GEMM (cp.async pipeline) --------
// out[n,:] = relu( [g_sum16(means) || h16[n,:]] @ Wcat + bias )
// BM=128, BN=128, BK=64, 3-stage cp.async. 8 warps 4x2, warp tile 32x64.
// m16n8k16 f16 with fp32 accumulate.
#define KCH     64
#define NCHUNK  (KTOT / KCH)            // 18
#define LDPH    72                      // padded smem row stride (halfs)
#define BUF_H   (2 * 128 * LDPH)        // halfs per stage (A+B)
#define NSTAGE  3
#define SMEM_TOT (NSTAGE * BUF_H * 2)   // 110592 B

__device__ __forceinline__ void mma_f16(float* c, const uint32_t* a,
                                        const uint32_t* b) {
    asm volatile(
        "mma.sync.aligned.m16n8k16.row.col.f32.f16.f16.f32 "
        "{%0,%1,%2,%3}, {%4,%5,%6,%7}, {%8,%9}, {%0,%1,%2,%3};"
        : "+f"(c[0]), "+f"(c[1]), "+f"(c[2]), "+f"(c[3])
        : "r"(a[0]), "r"(a[1]), "r"(a[2]), "r"(a[3]), "r"(b[0]), "r"(b[1]));
}

__global__ __launch_bounds__(256, 2) void rgcn_gemm_mma(
    int useGin, int wtSel, const float* __restrict__ bias, int outSel)
{
    extern __shared__ __half smemh[];
    const uint32_t smemBase = smem_u32(smemh);
    const int tid  = threadIdx.x;
    const int wid  = tid >> 5;
    const int lane = tid & 31;
    const int g    = lane >> 2;
    const int t4   = lane & 3;
    const int wr   = wid & 3;        // warp row (M: 4 x 32)
    const int wc   = wid >> 2;       // warp col (N: 2 x 64)
    const int row0 = blockIdx.x * 128;

    const __half* __restrict__ hin = useGin ? g_h116 : g_e16;
    const __half* __restrict__ WT  = wtSel ? g_WT116 : g_WT016;
    __half* __restrict__ hout = outSel ? g_h216 : g_h116;

    float acc[2][8][4];
#pragma unroll
    for (int mt = 0; mt < 2; ++mt)
#pragma unroll
        for (int nt = 0; nt < 8; ++nt)
#pragma unroll
            for (int j = 0; j < 4; ++j) acc[mt][nt][j] = 0.f;

    // ---- issue cp.async loads for chunk c into stage buf ----
    // Per chunk: A 128 rows x 64 halfs (8 granules/row), B same. 2048 granules.
    auto issue = [&](int buf, int c) {
        const int k0 = c * KCH;
        const bool isSum = (k0 < K0LIM);
        uint32_t aBase = smemBase + (uint32_t)(buf * BUF_H) * 2u;
        uint32_t bBase = aBase + 128u * LDPH * 2u;
#pragma unroll
        for (int it = 0; it < 8; ++it) {
            int idx = tid + it * 256;        // 0..2047
            int m = (idx & 1023) >> 3;
            int q = idx & 7;
            uint32_t off = (uint32_t)(m * LDPH + q * 8) * 2u;
            if (idx < 1024) {
                int n = row0 + m;
                bool ok = (n < NNODES);
                int nc = ok ? n : (NNODES - 1);
                const __half* srcA = isSum
                    ? (g_sum16 + (size_t)nc * K0LIM + k0 + q * 8)
                    : (hin + (size_t)nc * DIM + (k0 - K0LIM) + q * 8);
                cp16(aBase + off, srcA, ok);
            } else {
                cp16(bBase + off, WT + (size_t)m * KTOT + k0 + q * 8, true);
            }
        }
        asm volatile("cp.async.commit_group;" ::: "memory");
    };

    // ---- compute one k-chunk (4 k16-steps) from stage buf ----
    auto compute = [&](int buf) {
        const __half* smA = smemh + buf * BUF_H;
        const __half* smB = smA + 128 * LDPH;
#pragma unroll
        for (int ks = 0; ks < 4; ++ks) {
            const int kk = ks * 16;
            uint32_t a[2][4], b[8][2];
#pragma unroll
            for (int mt = 0; mt < 2; ++mt) {
                int r0 = wr * 32 + mt * 16 + g;
                a[mt][0] = *reinterpret_cast<const uint32_t*>(
                    smA + (r0)     * LDPH + kk + 2 * t4);
                a[mt][1] = *reinterpret_cast<const uint32_t*>(
                    smA + (r0 + 8) * LDPH + kk + 2 * t4);
                a[mt][2] = *reinterpret_cast<const uint32_t*>(
                    smA + (r0)     * LDPH + kk + 8 + 2 * t4);
                a[mt][3] = *reinterpret_cast<const uint32_t*>(
                    smA + (r0 + 8) * LDPH + kk + 8 + 2 * t4);
            }
#pragma unroll
            for (int nt = 0; nt < 8; ++nt) {
                int nn = wc * 64 + nt * 8 + g;
                b[nt][0] = *reinterpret_cast<const uint32_t*>(
                    smB + nn * LDPH + kk + 2 * t4);
                b[nt][1] = *reinterpret_cast<const uint32_t*>(
                    smB + nn * LDPH + kk + 8 + 2 * t4);
            }
#pragma unroll
            for (int mt = 0; mt < 2; ++mt)
#pragma unroll
                for (int nt = 0; nt < 8; ++nt)
                    mma_f16(acc[mt][nt], a[mt], b[nt]);
        }
    };

    // ---- 3-stage pipeline ----
    issue(0, 0);
    issue(1, 1);
    for (int c = 0; c < NCHUNK; ++c) {
        if (c + 2 < NCHUNK) {
            issue((c + 2) % NSTAGE, c + 2);
            asm volatile("cp.async.wait_group 2;" ::: "memory");
        } else if (c + 1 < NCHUNK) {
            asm volatile("cp.async.wait_group 1;" ::: "memory");
        } else {
            asm volatile("cp.async.wait_group 0;" ::: "memory");
        }
        __syncthreads();
        compute(c % NSTAGE);
        __syncthreads();
    }

    // ---- epilogue: bias + relu, write fp16 ----
    float2 bb[8];
#pragma unroll
    for (int nt = 0; nt < 8; ++nt) {
        int col = wc * 64 + nt * 8 + t4 * 2;
        bb[nt].x = __ldg(bias + col);
        bb[nt].y = __ldg(bias + col + 1);
    }
#pragma unroll
    for (int mt = 0; mt < 2; ++mt) {
        int r0 = row0 + wr * 32 + mt * 16 + g;
#pragma unroll
        for (int half = 0; half < 2; ++half) {
            int n = r0 + half * 8;
            if (n < NNODES) {
                __half* dst = hout + (size_t)n * DIM;
#pragma unroll
                for (int nt = 0; nt < 8; ++nt) {
                    int col = wc * 64 + nt * 8 + t4 * 2;
                    float ox = fmaxf(acc[mt][nt][half * 2 + 0] + bb[nt].x, 0.f);
                    float oy = fmaxf(acc[mt][nt][half * 2 + 1] + bb[nt].y, 0.f);
                    *reinterpret_cast<__half2*>(dst + col) =
                        __floats2half2_rn(ox, oy);
                }
            }
        }
    }
}

// ---------------- DistMult score: one warp per triple (fp16 h) ------------
__global__ void score_kernel(const float* __restrict__ rel_emb,
                             const int* __restrict__ head,
                             const int* __restrict__ rel,
                             const int* __restrict__ tail,
                             float* __restrict__ out) {
    int t    = (blockIdx.x * blockDim.x + threadIdx.x) >> 5;
    int lane = threadIdx.x & 31;
    if (t >= NTRIP) return;
    uint2 ar = reinterpret_cast<const uint2*>(
        g_h216 + (size_t)head[t] * DIM)[lane];
    uint2 br = reinterpret_cast<const uint2*>(
        g_h216 + (size_t)tail[t] * DIM)[lane];
    const float4 r = reinterpret_cast<const float4*>(
        rel_emb + (size_t)rel[t] * DIM)[lane];
    float2 a0 = __half22float2(*reinterpret_cast<__half2*>(&ar.x));
    float2 a1 = __half22float2(*reinterpret_cast<__half2*>(&ar.y));
    float2 b0 = __half22float2(*reinterpret_cast<__half2*>(&br.x));
    float2 b1 = __half22float2(*reinterpret_cast<__half2*>(&br.y));
    float s = a0.x * r.x * b0.x + a0.y * r.y * b0.y
            + a1.x * r.z * b1.x + a1.y * r.w * b1.y;
#pragma unroll
    for (int off = 16; off; off >>= 1)
        s += __shfl_xor_sync(0xFFFFFFFFu, s, off);
    if (lane == 0) out[t] = s;
}

// ---------------- launcher -------------------------------------------------
extern "C" void kernel_launch(void* const* d_in, const int* in_sizes, int n_in,
                              void* d_out, int out_size) {
    const float* emb   = (const float*)d_in[0];
    const float* W0    = (const float*)d_in[1];
    const float* root0 = (const float*)d_in[2];
    const float* b0    = (const float*)d_in[3];
    const float* W1    = (const float*)d_in[4];
    const float* root1 = (const float*)d_in[5];
    const float* b1    = (const float*)d_in[6];
    const float* relE  = (const float*)d_in[7];
    const int*   ei    = (const int*)d_in[8];
    const int*   et    = (const int*)d_in[9];
    const int*   hidx  = (const int*)d_in[10];
    const int*   ridx  = (const int*)d_in[11];
    const int*   tidx  = (const int*)d_in[12];
    float*       out   = (float*)d_out;

    static int smemSet = 0;
    if (!smemSet) {
        cudaFuncSetAttribute(rgcn_gemm_mma,
                             cudaFuncAttributeMaxDynamicSharedMemorySize,
                             SMEM_TOT);
        smemSet = 1;
    }

    const int edgeGrid  = (NEDGE + 255) / 256;          // 3125
    const int aggGrid   = (NSEG * 32 + 255) / 256;      // 50000
    const int gemmGrid  = (NNODES + 127) / 128;         // 391
    const int scoreGrid = (NTRIP * 32 + 255) / 256;     // 12500

    // one-time-per-call conversions (independent, cheap)
    conv_emb<<<4096, 256>>>(emb);
    transpose_w<<<2 * KTOT, 128>>>(W0, root0, W1, root1);

    // ----- CSR build (shared by both layers) -----
    csr_zero<<<1024, 256>>>();
    csr_hist<<<edgeGrid, 256>>>(ei, et);
    csr_bsum<<<NBLK, 1024>>>();
    csr_bscan<<<1, 512>>>();
    csr_off<<<NBLK, 1024>>>();
    csr_fill<<<edgeGrid, 256>>>(ei, et);

    // ----- layer 0 -----
    aggregate_kernel<<<aggGrid, 256>>>(0);
    rgcn_gemm_mma<<<gemmGrid, 256, SMEM_TOT>>>(0, /*wt*/0, b0, /*out*/0);

    // ----- layer 1 -----
    aggregate_kernel<<<aggGrid, 256>>>(1);
    rgcn_gemm_mma<<<gemmGrid, 256, SMEM_TOT>>>(1, /*wt*/1, b1, /*out*/1);

    // ----- DistMult score -----
    score_kernel<<<scoreGrid, 256>>>(relE, hidx, ridx, tidx, out);
}